// round 3
// baseline (speedup 1.0000x reference)
#include <cuda_runtime.h>
#include <cuda_bf16.h>

// Problem constants (fixed shapes for this dataset)
// B=4, N=1024, C=16, H=W=128
#define BB 4
#define NN 1024
#define CC 16
#define HW 128

// Scratch: ev transposed [b][gv][n], eu [b][n][gu] (+padding for prefetch overrun)
__device__ float g_ev[BB * HW * NN];
__device__ float g_eu[BB * NN * HW + 2048];

__device__ __forceinline__ float ex2f(float x) {
    float y;
    asm("ex2.approx.ftz.f32 %0, %1;" : "=f"(y) : "f"(x));
    return y;
}

// ---------------------------------------------------------------------------
// Kernel A: project points, compute separable Gaussian factors.
// ---------------------------------------------------------------------------
__global__ void __launch_bounds__(128) proj_kernel(
    const float* __restrict__ Kc,
    const float* __restrict__ RT,
    const float* __restrict__ pts3d,
    const float* __restrict__ scale)
{
    const int b  = blockIdx.x >> 5;
    const int n0 = (blockIdx.x & 31) << 5;
    const int tid = threadIdx.x;

    __shared__ float su[32], sv[32], sinv[32], smask[32];

    if (tid < 32) {
        const int n = n0 + tid;
        const float* rt = RT + b * 12;
        const float* p  = pts3d + (b * NN + n) * 3;
        float p0 = p[0], p1 = p[1], p2 = p[2];
        float l0 = rt[0] * p0 + rt[1] * p1 + rt[2]  * p2 + rt[3];
        float l1 = rt[4] * p0 + rt[5] * p1 + rt[6]  * p2 + rt[7];
        float l2 = rt[8] * p0 + rt[9] * p1 + rt[10] * p2 + rt[11];
        float x = Kc[0] * l0 + Kc[1] * l1 + Kc[2] * l2;
        float y = Kc[3] * l0 + Kc[4] * l1 + Kc[5] * l2;
        float z = Kc[6] * l0 + Kc[7] * l1 + Kc[8] * l2;
        float mask = (z > 0.1f) ? 1.0f : 0.0f;
        float zc = fmaxf(z, 0.1f);
        float sig = Kc[0] * 0.03125f;          // sigma = K[0,0]/32 (N != 1)
        float inv = 1.0f / (scale[b * NN + n] * sig * sig);
        su[tid]   = x / zc;
        sv[tid]   = y / zc;
        sinv[tid] = -1.4426950408889634f * inv; // fold -log2(e)
        smask[tid] = mask;
    }
    __syncthreads();

    const int warp = tid >> 5;
    const int lane = tid & 31;

    {
        const float v  = sv[lane];
        const float ni = sinv[lane];
        float* dst = g_ev + (b * HW) * NN + n0 + lane;
        #pragma unroll 8
        for (int j = 0; j < 32; j++) {
            const int gv = warp * 32 + j;
            float d = v - (float)gv;
            dst[gv * NN] = ex2f(d * d * ni);
        }
    }
    {
        const float fgu = (float)tid;
        float* dst = g_eu + (b * NN + n0) * HW + tid;
        #pragma unroll 8
        for (int i = 0; i < 32; i++) {
            float d = su[i] - fgu;
            dst[i * HW] = ex2f(d * d * sinv[i]) * smask[i];
        }
    }
}

// ---------------------------------------------------------------------------
// Kernel B: img[b,c,gv,gu] = sum_n feat[b,n,c] * ev[b,n,gv] * eu[b,n,gu]
// grid = B*32 = 128 blocks; block = (b, 4 gv rows); 1024 threads:
//   tid = gu | csel<<7 | rsel<<8 | nsel<<9
//   gu   : pixel column (128)
//   csel : channel half (ch 0-7 / 8-15)
//   rsel : row pair (gv0+{0,1} / gv0+{2,3})   -- no duplicated work
//   nsel : n half ([0,512) / [512,1024))      -- combined via smem reduce
// 32 warps/SM (occ 50%), 8 warps/SMSP; acc = 2 rows x 4 c-pairs = 16 regs.
// ---------------------------------------------------------------------------
__global__ void __launch_bounds__(1024, 1) accum_kernel(
    const float* __restrict__ feat,
    float* __restrict__ out)
{
    const int b   = blockIdx.x >> 5;
    const int gv0 = (blockIdx.x & 31) << 2;
    const int tid  = threadIdx.x;
    const int gu   = tid & 127;
    const int csel = (tid >> 7) & 1;
    const int rsel = (tid >> 8) & 1;
    const int nsel = tid >> 9;

    __shared__ float sfeat[2][128][16];              // per n-group feat chunk (16KB)
    __shared__ unsigned long long sev2[2][4][128];   // per n-group (ev,ev) pairs (8KB)

    const float* evb   = g_ev + (b * HW + gv0) * NN;
    const float* eub   = g_eu + b * NN * HW + gu;
    const float* featb = feat + b * NN * CC;

    unsigned long long acc[2][4];
    #pragma unroll
    for (int r = 0; r < 2; r++)
        #pragma unroll
        for (int c = 0; c < 4; c++) acc[r][c] = 0ULL;

    const int nbase = nsel << 9;  // 0 or 512
    const int rbase = rsel << 1;  // 0 or 2

    float eu_cur[4], eu_nxt[4];
    #pragma unroll
    for (int u = 0; u < 4; u++) eu_cur[u] = eub[(nbase + u) * HW];

    for (int chunk = 0; chunk < 4; chunk++) {
        __syncthreads();
        // ---- stage this chunk for both n-groups (each thread: 1 float4 + 1 ev) ----
        {
            const int g  = tid >> 9;
            const int nl = (tid >> 2) & 127;
            const int pt = tid & 3;
            const int nf = (g << 9) + chunk * 128 + nl;
            reinterpret_cast<float4*>(&sfeat[g][nl][0])[pt] =
                reinterpret_cast<const float4*>(featb + nf * CC)[pt];

            const int r  = (tid >> 7) & 3;
            const int ne = tid & 127;
            float e = evb[r * NN + (g << 9) + chunk * 128 + ne];
            unsigned long long ep;
            asm("mov.b64 %0, {%1, %1};" : "=l"(ep) : "f"(e));
            sev2[g][r][ne] = ep;
        }
        __syncthreads();

        #pragma unroll 1
        for (int j = 0; j < 128; j += 4) {
            // prefetch next 4 eu values (g_eu padding absorbs final overrun)
            const float* pf = eub + (nbase + chunk * 128 + j + 4) * HW;
            #pragma unroll
            for (int u = 0; u < 4; u++) eu_nxt[u] = pf[u * HW];

            #pragma unroll
            for (int u = 0; u < 4; u++) {
                const int n = j + u;
                unsigned long long eup;
                asm("mov.b64 %0, {%1, %1};" : "=l"(eup) : "f"(eu_cur[u]));
                unsigned long long f[4];
                const unsigned long long* fp =
                    reinterpret_cast<const unsigned long long*>(&sfeat[nsel][n][csel << 3]);
                #pragma unroll
                for (int c = 0; c < 4; c++) f[c] = fp[c];
                #pragma unroll
                for (int r = 0; r < 2; r++) {
                    unsigned long long wp;
                    asm("mul.rn.f32x2 %0, %1, %2;"
                        : "=l"(wp) : "l"(sev2[nsel][rbase + r][n]), "l"(eup));
                    #pragma unroll
                    for (int c = 0; c < 4; c++)
                        asm("fma.rn.f32x2 %0, %1, %2, %0;"
                            : "+l"(acc[r][c]) : "l"(f[c]), "l"(wp));
                }
            }
            #pragma unroll
            for (int u = 0; u < 4; u++) eu_cur[u] = eu_nxt[u];
        }
    }

    // ---- combine the two n-halves via shared memory (2 passes of 1 row) ----
    unsigned long long* sred = reinterpret_cast<unsigned long long*>(&sfeat[0][0][0]);
    const int s = tid & 511;  // (rsel,csel,gu) composite index
    #pragma unroll
    for (int r = 0; r < 2; r++) {
        __syncthreads();
        if (nsel == 1) {
            #pragma unroll
            for (int c = 0; c < 4; c++) sred[s * 4 + c] = acc[r][c];
        }
        __syncthreads();
        if (nsel == 0) {
            #pragma unroll
            for (int c = 0; c < 4; c++)
                asm("add.rn.f32x2 %0, %0, %1;"
                    : "+l"(acc[r][c]) : "l"(sred[s * 4 + c]));
        }
    }

    // ---- write out[b][c][gv][gu] (nsel==0 threads only) ----
    if (nsel == 0) {
        float* ob = out + (b * CC + (csel << 3)) * (HW * HW) + (gv0 + rbase) * HW + gu;
        #pragma unroll
        for (int r = 0; r < 2; r++) {
            #pragma unroll
            for (int c = 0; c < 4; c++) {
                float lo, hi;
                asm("mov.b64 {%0, %1}, %2;" : "=f"(lo), "=f"(hi) : "l"(acc[r][c]));
                ob[(2 * c)     * (HW * HW) + r * HW] = lo;
                ob[(2 * c + 1) * (HW * HW) + r * HW] = hi;
            }
        }
    }
}

extern "C" void kernel_launch(void* const* d_in, const int* in_sizes, int n_in,
                              void* d_out, int out_size)
{
    const float* Kc    = (const float*)d_in[0];
    const float* RT    = (const float*)d_in[1];
    const float* pts3d = (const float*)d_in[2];
    const float* feat  = (const float*)d_in[3];
    const float* scale = (const float*)d_in[4];
    float* out = (float*)d_out;

    proj_kernel<<<BB * NN / 32, 128>>>(Kc, RT, pts3d, scale);
    accum_kernel<<<BB * 32, 1024>>>(feat, out);
}

// round 4
// speedup vs baseline: 1.2628x; 1.2628x over previous
#include <cuda_runtime.h>
#include <cuda_bf16.h>

// Problem constants (fixed shapes for this dataset)
// B=4, N=1024, C=16, H=W=128
#define BB 4
#define NN 1024
#define CC 16
#define HW 128

// Scratch: ev transposed [b][gv][n], eu [b][n][gu] (+padding for prefetch overrun)
__device__ float g_ev[BB * HW * NN];
__device__ float g_eu[BB * NN * HW + 2048];

__device__ __forceinline__ float ex2f(float x) {
    float y;
    asm("ex2.approx.ftz.f32 %0, %1;" : "=f"(y) : "f"(x));
    return y;
}

// ---------------------------------------------------------------------------
// Kernel A: project points, compute separable Gaussian factors.
// ---------------------------------------------------------------------------
__global__ void __launch_bounds__(128) proj_kernel(
    const float* __restrict__ Kc,
    const float* __restrict__ RT,
    const float* __restrict__ pts3d,
    const float* __restrict__ scale)
{
    const int b  = blockIdx.x >> 5;
    const int n0 = (blockIdx.x & 31) << 5;
    const int tid = threadIdx.x;

    __shared__ float su[32], sv[32], sinv[32], smask[32];

    if (tid < 32) {
        const int n = n0 + tid;
        const float* rt = RT + b * 12;
        const float* p  = pts3d + (b * NN + n) * 3;
        float p0 = p[0], p1 = p[1], p2 = p[2];
        float l0 = rt[0] * p0 + rt[1] * p1 + rt[2]  * p2 + rt[3];
        float l1 = rt[4] * p0 + rt[5] * p1 + rt[6]  * p2 + rt[7];
        float l2 = rt[8] * p0 + rt[9] * p1 + rt[10] * p2 + rt[11];
        float x = Kc[0] * l0 + Kc[1] * l1 + Kc[2] * l2;
        float y = Kc[3] * l0 + Kc[4] * l1 + Kc[5] * l2;
        float z = Kc[6] * l0 + Kc[7] * l1 + Kc[8] * l2;
        float mask = (z > 0.1f) ? 1.0f : 0.0f;
        float zc = fmaxf(z, 0.1f);
        float sig = Kc[0] * 0.03125f;          // sigma = K[0,0]/32 (N != 1)
        float inv = 1.0f / (scale[b * NN + n] * sig * sig);
        su[tid]   = x / zc;
        sv[tid]   = y / zc;
        sinv[tid] = -1.4426950408889634f * inv; // fold -log2(e)
        smask[tid] = mask;
    }
    __syncthreads();

    const int warp = tid >> 5;
    const int lane = tid & 31;

    {
        const float v  = sv[lane];
        const float ni = sinv[lane];
        float* dst = g_ev + (b * HW) * NN + n0 + lane;
        #pragma unroll 8
        for (int j = 0; j < 32; j++) {
            const int gv = warp * 32 + j;
            float d = v - (float)gv;
            dst[gv * NN] = ex2f(d * d * ni);
        }
    }
    {
        const float fgu = (float)tid;
        float* dst = g_eu + (b * NN + n0) * HW + tid;
        #pragma unroll 8
        for (int i = 0; i < 32; i++) {
            float d = su[i] - fgu;
            dst[i * HW] = ex2f(d * d * sinv[i]) * smask[i];
        }
    }
}

// ---------------------------------------------------------------------------
// Kernel B: img[b,c,gv,gu] = sum_n feat[b,n,c] * ev[b,n,gv] * eu[b,n,gu]
// grid = B*32 = 128 blocks; block = (b, 4 gv rows); 512 threads:
//   tid = gu | csel<<7 | nsel<<8
//   gu   : pixel column (128)
//   csel : channel half (ch 0-7 / 8-15)
//   nsel : n half ([0,512) / [512,1024))  -> combined via smem reduce
// All inner-loop shared loads are warp-uniform broadcasts, widened to LDS.128:
//   feat : 2x LDS.128 (8ch contiguous), ev: 2x LDS.128 (n-major [n][r] layout).
// Per thread-n: 20 fma-pipe ops vs 4 LDS -> FMA-pipe bound with 2.5x MIO margin.
// ---------------------------------------------------------------------------
__global__ void __launch_bounds__(512, 1) accum_kernel(
    const float* __restrict__ feat,
    float* __restrict__ out)
{
    const int b   = blockIdx.x >> 5;
    const int gv0 = (blockIdx.x & 31) << 2;   // 4 rows per block
    const int tid  = threadIdx.x;
    const int gu   = tid & 127;
    const int csel = (tid >> 7) & 1;
    const int nsel = tid >> 8;

    __shared__ float sfeat[2][128][16];              // per n-group feat chunk (16KB)
    __shared__ unsigned long long sev2[2][128][4];   // (ev,ev) pairs, n-major (8KB)

    const float* evb   = g_ev + (b * HW + gv0) * NN;
    const float* eub   = g_eu + b * NN * HW + gu;
    const float* featb = feat + b * NN * CC;

    unsigned long long acc[4][4];
    #pragma unroll
    for (int r = 0; r < 4; r++)
        #pragma unroll
        for (int c = 0; c < 4; c++) acc[r][c] = 0ULL;

    const int nbase = nsel << 9;  // 0 or 512

    float eu_cur[8], eu_nxt[8];
    #pragma unroll
    for (int u = 0; u < 8; u++) eu_cur[u] = eub[(nbase + u) * HW];

    for (int chunk = 0; chunk < 4; chunk++) {
        const int n0 = chunk * 128;
        __syncthreads();
        // ---- stage this chunk for both n-groups (512 threads cooperate) ----
        {
            // feat: thread covers one n-row of one group via float4 x2
            const int gf = tid >> 8;               // group
            const int nl = tid & 255;              // 0..255 -> (n, half-row)
            const int nf = nl >> 1;
            const int pt = (nl & 1) << 1;          // float4 index 0 or 2
            const float4* s4 =
                reinterpret_cast<const float4*>(featb + ((gf << 9) + n0 + nf) * CC);
            float4* d4 = reinterpret_cast<float4*>(&sfeat[gf][nf][0]);
            d4[pt]     = s4[pt];
            d4[pt + 1] = s4[pt + 1];

            // ev: thread covers rows {r2, r2+2} for one n of one group (n-major layout)
            const int ge = tid >> 8;
            const int r2 = (tid >> 7) & 1;
            const int ne = tid & 127;
            #pragma unroll
            for (int k = 0; k < 2; k++) {
                const int r = r2 + k * 2;
                float e = evb[r * NN + (ge << 9) + n0 + ne];
                unsigned long long ep;
                asm("mov.b64 %0, {%1, %1};" : "=l"(ep) : "f"(e));
                sev2[ge][ne][r] = ep;
            }
        }
        __syncthreads();

        #pragma unroll 1
        for (int j = 0; j < 128; j += 8) {
            // prefetch next 8 eu values (g_eu padding absorbs final overrun)
            const float* pf = eub + (nbase + n0 + j + 8) * HW;
            #pragma unroll
            for (int u = 0; u < 8; u++) eu_nxt[u] = pf[u * HW];

            #pragma unroll
            for (int u = 0; u < 8; u++) {
                const int n = j + u;
                unsigned long long eup;
                asm("mov.b64 %0, {%1, %1};" : "=l"(eup) : "f"(eu_cur[u]));

                // 2x LDS.128: 8 feat channels (uniform broadcast)
                ulonglong2 f01 = *reinterpret_cast<const ulonglong2*>(
                    &sfeat[nsel][n][csel << 3]);
                ulonglong2 f23 = *reinterpret_cast<const ulonglong2*>(
                    &sfeat[nsel][n][(csel << 3) + 4]);
                unsigned long long f[4] = {f01.x, f01.y, f23.x, f23.y};

                // 2x LDS.128: 4 ev row-pairs (uniform broadcast)
                ulonglong2 e01 = *reinterpret_cast<const ulonglong2*>(&sev2[nsel][n][0]);
                ulonglong2 e23 = *reinterpret_cast<const ulonglong2*>(&sev2[nsel][n][2]);
                unsigned long long ev4[4] = {e01.x, e01.y, e23.x, e23.y};

                #pragma unroll
                for (int r = 0; r < 4; r++) {
                    unsigned long long wp;
                    asm("mul.rn.f32x2 %0, %1, %2;"
                        : "=l"(wp) : "l"(ev4[r]), "l"(eup));
                    #pragma unroll
                    for (int c = 0; c < 4; c++)
                        asm("fma.rn.f32x2 %0, %1, %2, %0;"
                            : "+l"(acc[r][c]) : "l"(f[c]), "l"(wp));
                }
            }
            #pragma unroll
            for (int u = 0; u < 8; u++) eu_cur[u] = eu_nxt[u];
        }
    }

    // ---- combine the two n-halves via shared memory (2 passes of 2 rows) ----
    unsigned long long* sred = reinterpret_cast<unsigned long long*>(&sfeat[0][0][0]);
    const int s = (csel << 7) + gu;  // 0..255
    #pragma unroll
    for (int half = 0; half < 2; half++) {
        __syncthreads();
        if (nsel == 1) {
            #pragma unroll
            for (int r2 = 0; r2 < 2; r2++)
                #pragma unroll
                for (int c = 0; c < 4; c++)
                    sred[s * 8 + r2 * 4 + c] = acc[half * 2 + r2][c];
        }
        __syncthreads();
        if (nsel == 0) {
            #pragma unroll
            for (int r2 = 0; r2 < 2; r2++)
                #pragma unroll
                for (int c = 0; c < 4; c++)
                    asm("add.rn.f32x2 %0, %0, %1;"
                        : "+l"(acc[half * 2 + r2][c]) : "l"(sred[s * 8 + r2 * 4 + c]));
        }
    }

    // ---- write out[b][c][gv][gu] (nsel==0 threads only) ----
    if (nsel == 0) {
        float* ob = out + (b * CC + (csel << 3)) * (HW * HW) + gv0 * HW + gu;
        #pragma unroll
        for (int r = 0; r < 4; r++) {
            #pragma unroll
            for (int c = 0; c < 4; c++) {
                float lo, hi;
                asm("mov.b64 {%0, %1}, %2;" : "=f"(lo), "=f"(hi) : "l"(acc[r][c]));
                ob[(2 * c)     * (HW * HW) + r * HW] = lo;
                ob[(2 * c + 1) * (HW * HW) + r * HW] = hi;
            }
        }
    }
}

extern "C" void kernel_launch(void* const* d_in, const int* in_sizes, int n_in,
                              void* d_out, int out_size)
{
    const float* Kc    = (const float*)d_in[0];
    const float* RT    = (const float*)d_in[1];
    const float* pts3d = (const float*)d_in[2];
    const float* feat  = (const float*)d_in[3];
    const float* scale = (const float*)d_in[4];
    float* out = (float*)d_out;

    proj_kernel<<<BB * NN / 32, 128>>>(Kc, RT, pts3d, scale);
    accum_kernel<<<BB * 32, 512>>>(feat, out);
}

// round 6
// speedup vs baseline: 2.6399x; 2.0905x over previous
#include <cuda_runtime.h>
#include <cuda_fp16.h>
#include <cstdint>

// Problem constants: B=4, N=1024, C=16, H=W=128
#define BB 4
#define NN 1024
#define CC 16
#define HW 128

// Scratch: ev [b][gv][n], eu [b][n][gu]
__device__ float g_ev[BB * HW * NN];
__device__ float g_eu[BB * NN * HW + 2048];

__device__ __forceinline__ float ex2f(float x) {
    float y;
    asm("ex2.approx.ftz.f32 %0, %1;" : "=f"(y) : "f"(x));
    return y;
}

__device__ __forceinline__ uint32_t smem_u32(const void* p) {
    uint32_t a;
    asm("{ .reg .u64 t; cvta.to.shared.u64 t, %1; cvt.u32.u64 %0, t; }"
        : "=r"(a) : "l"(p));
    return a;
}

#define SW128(o) ((o) ^ (((o) >> 3) & 0x70))

__device__ __forceinline__ void ldsm_x4(uint32_t* r, uint32_t addr) {
    asm volatile("ldmatrix.sync.aligned.m8n8.x4.shared.b16 {%0,%1,%2,%3}, [%4];"
                 : "=r"(r[0]), "=r"(r[1]), "=r"(r[2]), "=r"(r[3]) : "r"(addr));
}

__device__ __forceinline__ void mma16816(float* d, const uint32_t* a,
                                         const uint32_t* b) {
    asm volatile(
        "mma.sync.aligned.m16n8k16.row.col.f32.f16.f16.f32 "
        "{%0,%1,%2,%3}, {%4,%5,%6,%7}, {%8,%9}, {%0,%1,%2,%3};"
        : "+f"(d[0]), "+f"(d[1]), "+f"(d[2]), "+f"(d[3])
        : "r"(a[0]), "r"(a[1]), "r"(a[2]), "r"(a[3]), "r"(b[0]), "r"(b[1]));
}

// ---------------------------------------------------------------------------
// Kernel A: project points, compute separable Gaussian factors (unchanged).
// ---------------------------------------------------------------------------
__global__ void __launch_bounds__(128) proj_kernel(
    const float* __restrict__ Kc,
    const float* __restrict__ RT,
    const float* __restrict__ pts3d,
    const float* __restrict__ scale)
{
    const int b  = blockIdx.x >> 5;
    const int n0 = (blockIdx.x & 31) << 5;
    const int tid = threadIdx.x;

    __shared__ float su[32], sv[32], sinv[32], smask[32];

    if (tid < 32) {
        const int n = n0 + tid;
        const float* rt = RT + b * 12;
        const float* p  = pts3d + (b * NN + n) * 3;
        float p0 = p[0], p1 = p[1], p2 = p[2];
        float l0 = rt[0] * p0 + rt[1] * p1 + rt[2]  * p2 + rt[3];
        float l1 = rt[4] * p0 + rt[5] * p1 + rt[6]  * p2 + rt[7];
        float l2 = rt[8] * p0 + rt[9] * p1 + rt[10] * p2 + rt[11];
        float x = Kc[0] * l0 + Kc[1] * l1 + Kc[2] * l2;
        float y = Kc[3] * l0 + Kc[4] * l1 + Kc[5] * l2;
        float z = Kc[6] * l0 + Kc[7] * l1 + Kc[8] * l2;
        float mask = (z > 0.1f) ? 1.0f : 0.0f;
        float zc = fmaxf(z, 0.1f);
        float sig = Kc[0] * 0.03125f;            // sigma = K[0,0]/32
        float inv = 1.0f / (scale[b * NN + n] * sig * sig);
        su[tid]   = x / zc;
        sv[tid]   = y / zc;
        sinv[tid] = -1.4426950408889634f * inv;  // fold -log2(e)
        smask[tid] = mask;
    }
    __syncthreads();

    const int warp = tid >> 5;
    const int lane = tid & 31;

    {
        const float v  = sv[lane];
        const float ni = sinv[lane];
        float* dst = g_ev + (b * HW) * NN + n0 + lane;
        #pragma unroll 8
        for (int j = 0; j < 32; j++) {
            const int gv = warp * 32 + j;
            float d = v - (float)gv;
            dst[gv * NN] = ex2f(d * d * ni);
        }
    }
    {
        const float fgu = (float)tid;
        float* dst = g_eu + (b * NN + n0) * HW + tid;
        #pragma unroll 8
        for (int i = 0; i < 32; i++) {
            float d = su[i] - fgu;
            dst[i * HW] = ex2f(d * d * sinv[i]) * smask[i];
        }
    }
}

// ---------------------------------------------------------------------------
// Kernel B: HMMA GEMM.  D[gu,c] = sum_n W[gu,n] * feat[n,c]  per gv row.
// grid = 128 CTAs = (b, 4 gv rows), 512 threads.
// Per 64-n chunk: build 4 f16 W tiles [128gu x 64n] (SW128 rows) in smem,
// consume via ldmatrix + mma.m16n8k16 (f32 acc in regs).
// Double-buffered W: build(k) overlaps consume(k-1); one sync per chunk.
// Warp wid: mt = wid&7 (gu tile of 16), rp = wid>>3 (rows rp*2+{0,1}).
// ---------------------------------------------------------------------------
#define W_BYTES   65536u                 // one buffer: 4 rows x 16KB
#define FT_OFF    131072u                // featT [16 c][1024+8 k] f16
#define FT_STRIDE 2064u                  // (1024+8)*2 bytes; 516 words -> cf banks
#define EV_OFF    164096u                // sev [4 r][1024 n] f32 = 16KB
#define SMEM_DYN  181504u                // 180480 + align slack

__global__ void __launch_bounds__(512, 1) accum_kernel(
    const float* __restrict__ feat,
    float* __restrict__ out)
{
    extern __shared__ char smem_raw[];
    const uint32_t raw = smem_u32(smem_raw);
    const uint32_t sb  = (raw + 1023) & ~1023u;
    char* smem = smem_raw + (sb - raw);

    const int b   = blockIdx.x >> 5;
    const int gv0 = (blockIdx.x & 31) << 2;
    const int t    = threadIdx.x;
    const int wid  = t >> 5;
    const int lane = t & 31;

    // ---- stage featT: [c][k] f16, padded rows (conflict-free B loads) ----
    {
        const int c  = t & 15;
        const int nv = t >> 4;
        const float* fb = feat + (size_t)b * NN * CC;
        #pragma unroll 8
        for (int i = 0; i < 32; i++) {
            const int n = nv + 32 * i;
            float v = fb[(size_t)n * CC + c];
            *(__half*)(smem + FT_OFF + c * FT_STRIDE + n * 2) = __float2half(v);
        }
    }
    // ---- stage ev: sev[r][n] f32 ----
    {
        const int r  = t >> 7;
        const int i8 = (t & 127) * 8;
        const float* evb = g_ev + (size_t)(b * HW + gv0 + r) * NN + i8;
        float* dst = (float*)(smem + EV_OFF) + r * NN + i8;
        *(float4*)dst       = *(const float4*)evb;
        *(float4*)(dst + 4) = *(const float4*)(evb + 4);
    }

    // build-thread mapping: gu pair (gu0, gu0+1), k-slice nsl (8 n each)
    const int gu0 = (t & 63) * 2;
    const int nsl = t >> 6;                 // 0..7, warp-uniform
    const float* eub = g_eu + (size_t)b * NN * HW + gu0;
    const float* sev = (const float*)(smem + EV_OFF);

    float2 euA[8], euB[8];
    #pragma unroll
    for (int j = 0; j < 8; j++)
        euA[j] = *(const float2*)(eub + (size_t)(nsl * 8 + j) * HW);

    __syncthreads();   // staging complete

    // consumer mapping
    const int mt = wid & 7;
    const int rp = wid >> 3;
    float acc[2][2][4];
    #pragma unroll
    for (int rr = 0; rr < 2; rr++)
        #pragma unroll
        for (int nt = 0; nt < 2; nt++)
            #pragma unroll
            for (int q = 0; q < 4; q++) acc[rr][nt][q] = 0.0f;

    // ldmatrix lane row/col (constant per thread)
    const uint32_t lrow = (uint32_t)(mt * 16 + (lane & 15));
    const uint32_t lkb  = (uint32_t)((lane >> 4) * 16);
    const uint32_t bcol_off = FT_OFF + (uint32_t)((lane >> 2) * FT_STRIDE)
                            + (uint32_t)((lane & 3) * 4);

    for (int k = 0; k < 16; k++) {
        const int nb = k * 64;
        // prefetch eu for next chunk
        if (k < 15) {
            #pragma unroll
            for (int j = 0; j < 8; j++)
                euB[j] = *(const float2*)(eub + (size_t)(nb + 64 + nsl * 8 + j) * HW);
        }
        // ---- build W chunk k into buffer k&1 ----
        {
            char* wbuf = smem + (k & 1) * W_BYTES;
            #pragma unroll
            for (int r = 0; r < 4; r++) {
                const float* se = sev + r * NN + nb + nsl * 8;
                uint32_t q0[4], q1[4];
                #pragma unroll
                for (int jj = 0; jj < 4; jj++) {
                    float2 e = *(const float2*)(se + 2 * jj);     // ev[n], ev[n+1]
                    float w00 = e.x * euA[2 * jj].x;
                    float w01 = e.x * euA[2 * jj].y;
                    float w10 = e.y * euA[2 * jj + 1].x;
                    float w11 = e.y * euA[2 * jj + 1].y;
                    // pack along n: lo = n, hi = n+1
                    asm("cvt.rn.f16x2.f32 %0, %1, %2;" : "=r"(q0[jj]) : "f"(w10), "f"(w00));
                    asm("cvt.rn.f16x2.f32 %0, %1, %2;" : "=r"(q1[jj]) : "f"(w11), "f"(w01));
                }
                const uint32_t o0 = (uint32_t)(gu0 * 128 + nsl * 16);
                const uint32_t o1 = o0 + 128;
                *(uint4*)(wbuf + r * 16384 + SW128(o0)) =
                    make_uint4(q0[0], q0[1], q0[2], q0[3]);
                *(uint4*)(wbuf + r * 16384 + SW128(o1)) =
                    make_uint4(q1[0], q1[1], q1[2], q1[3]);
            }
        }
        __syncthreads();   // W chunk k complete everywhere

        // ---- consume chunk k ----
        {
            const uint32_t wb = sb + (uint32_t)(k & 1) * W_BYTES;
            #pragma unroll
            for (int ks = 0; ks < 4; ks++) {
                // B fragments: featT[c][kglobal], k pairs contiguous
                uint32_t bf[2][2];
                const uint32_t kb2 = (uint32_t)((nb + ks * 16) * 2);
                #pragma unroll
                for (int nt = 0; nt < 2; nt++) {
                    const char* ba = smem + bcol_off + nt * 8 * FT_STRIDE + kb2;
                    bf[nt][0] = *(const uint32_t*)ba;
                    bf[nt][1] = *(const uint32_t*)(ba + 16);
                }
                #pragma unroll
                for (int rr = 0; rr < 2; rr++) {
                    const int r = rp * 2 + rr;
                    uint32_t a[4];
                    const uint32_t ao = lrow * 128 + (uint32_t)(ks * 32) + lkb;
                    ldsm_x4(a, wb + r * 16384 + SW128(ao));
                    mma16816(acc[rr][0], a, bf[0]);
                    mma16816(acc[rr][1], a, bf[1]);
                }
            }
        }
        #pragma unroll
        for (int j = 0; j < 8; j++) euA[j] = euB[j];
    }

    // ---- epilogue: D[gu_local][c] -> out[b][c][gv][gu] ----
    {
        const int guw = mt * 16 + (lane >> 2);
        const int c0w = (lane & 3) * 2;
        #pragma unroll
        for (int rr = 0; rr < 2; rr++) {
            const int gv = gv0 + rp * 2 + rr;
            float* ob = out + (size_t)b * CC * HW * HW + (size_t)gv * HW;
            #pragma unroll
            for (int nt = 0; nt < 2; nt++) {
                const int c = nt * 8 + c0w;
                ob[(size_t)c * HW * HW + guw]           = acc[rr][nt][0];
                ob[(size_t)(c + 1) * HW * HW + guw]     = acc[rr][nt][1];
                ob[(size_t)c * HW * HW + guw + 8]       = acc[rr][nt][2];
                ob[(size_t)(c + 1) * HW * HW + guw + 8] = acc[rr][nt][3];
            }
        }
    }
}

extern "C" void kernel_launch(void* const* d_in, const int* in_sizes, int n_in,
                              void* d_out, int out_size)
{
    const float* Kc    = (const float*)d_in[0];
    const float* RT    = (const float*)d_in[1];
    const float* pts3d = (const float*)d_in[2];
    const float* feat  = (const float*)d_in[3];
    const float* scale = (const float*)d_in[4];
    float* out = (float*)d_out;

    cudaFuncSetAttribute(accum_kernel,
                         cudaFuncAttributeMaxDynamicSharedMemorySize, SMEM_DYN);

    proj_kernel<<<BB * NN / 32, 128>>>(Kc, RT, pts3d, scale);
    accum_kernel<<<BB * 32, 512, SMEM_DYN>>>(feat, out);
}